// round 12
// baseline (speedup 1.0000x reference)
#include <cuda_runtime.h>
#include <cuda_fp16.h>
#include <cstdint>
#include <math_constants.h>

#define D       256
#define NT      65536
#define NE      4096
#define WINDOW  0.4f

// ---- smem layout (bytes) ----
#define APITCH  528                       // 264 halves per A row (256 data + 8 pad)
#define AH_OFF  0
#define BB_OFF  (128 * APITCH)            // 67584
#define BPITCH  144                       // 72 halves per B row (64 data + 8 pad)
#define BSTAGE  (128 * BPITCH)            // 18432
#define NSTAGE  2
#define RED_OFF BB_OFF                    // reduction arrays alias B stages
#define SMEM_TOTAL (BB_OFF + NSTAGE * BSTAGE)   // 104448 (~102KB) -> 2 CTAs/SM

__device__ float  g_eNormHalf[NE];
__device__ int    g_idx[NT];
__device__ int    g_ambCount;
__device__ int    g_fullCount;
__device__ int    g_ambList[NT];
__device__ int    g_fullList[NT];
__device__ int    g_candList[NT * 16];
__device__ int    g_candCnt[NT];
__device__ __half g_eH[NE * D];

// ---------------- helpers ----------------
__device__ __forceinline__ uint32_t smem_u32(const void* p) {
    uint32_t a;
    asm("{ .reg .u64 t; cvta.to.shared.u64 t, %1; cvt.u32.u64 %0, t; }" : "=r"(a) : "l"(p));
    return a;
}
__device__ __forceinline__ void ldsm4(uint32_t (&r)[4], uint32_t a) {
    asm volatile("ldmatrix.sync.aligned.m8n8.x4.shared.b16 {%0,%1,%2,%3}, [%4];"
                 : "=r"(r[0]), "=r"(r[1]), "=r"(r[2]), "=r"(r[3]) : "r"(a));
}
// fp16-accumulator MMA: D,C are 2x b32 (4 halves)
__device__ __forceinline__ void mma16816h(uint32_t (&c)[2], const uint32_t (&a)[4],
                                          uint32_t b0, uint32_t b1) {
    asm volatile("mma.sync.aligned.m16n8k16.row.col.f16.f16.f16.f16 "
                 "{%0,%1}, {%2,%3,%4,%5}, {%6,%7}, {%0,%1};"
                 : "+r"(c[0]), "+r"(c[1])
                 : "r"(a[0]), "r"(a[1]), "r"(a[2]), "r"(a[3]), "r"(b0), "r"(b1));
}

// exact fp32 score in the VALIDATED order (matches reference argmin behavior)
__device__ __forceinline__ float exact_score(const float* __restrict__ zrow,
                                             const float* __restrict__ e, int n) {
    float acc = 0.f;
    const float4* er = (const float4*)(e + (size_t)n * D);
    const float4* zr = (const float4*)zrow;
    #pragma unroll 8
    for (int k4 = 0; k4 < D / 4; k4++) {
        float4 ee = er[k4], zz = zr[k4];
        acc = __fmaf_rn(zz.x, ee.x, acc);
        acc = __fmaf_rn(zz.y, ee.y, acc);
        acc = __fmaf_rn(zz.z, ee.z, acc);
        acc = __fmaf_rn(zz.w, ee.w, acc);
    }
    return g_eNormHalf[n] - acc;
}

// ---------------------------------------------------------------------------
// prep: 0.5*||e||^2 AND fp16 image of e in one pass; zero counters.
// ---------------------------------------------------------------------------
__global__ void prep_kernel(const float* __restrict__ e) {
    int row  = blockIdx.x * (blockDim.x >> 5) + (threadIdx.x >> 5);
    int lane = threadIdx.x & 31;
    if (blockIdx.x == 0 && threadIdx.x == 0) { g_ambCount = 0; g_fullCount = 0; }
    const float4* p = (const float4*)(e + (size_t)row * D);
    float s = 0.f;
    #pragma unroll
    for (int i = 0; i < 2; i++) {
        int c4 = lane + i * 32;
        float4 v = p[c4];
        s += v.x * v.x + v.y * v.y + v.z * v.z + v.w * v.w;
        uint2 hv;
        hv.x = (uint32_t)__half_as_ushort(__float2half_rn(v.x)) |
               ((uint32_t)__half_as_ushort(__float2half_rn(v.y)) << 16);
        hv.y = (uint32_t)__half_as_ushort(__float2half_rn(v.z)) |
               ((uint32_t)__half_as_ushort(__float2half_rn(v.w)) << 16);
        *(uint2*)(g_eH + (size_t)row * D + c4 * 4) = hv;
    }
    #pragma unroll
    for (int o = 16; o; o >>= 1) s += __shfl_xor_sync(0xFFFFFFFFu, s, o);
    if (lane == 0) g_eNormHalf[row] = 0.5f * s;
}

// ---------------------------------------------------------------------------
// cp.async fill of one e k-chunk (128 codes x 64 dims fp16) into stage c%2
// ---------------------------------------------------------------------------
__device__ __forceinline__ void issue_chunk(uint32_t sbase, int c, int tid) {
    const int n0 = (c >> 2) * 128;
    const int k0 = (c & 3) * 64;
    const uint32_t sb = sbase + BB_OFF + (uint32_t)(c & 1) * BSTAGE;
    #pragma unroll
    for (int j = 0; j < 4; j++) {
        int lin = tid + j * 256;            // 0..1023
        int row = lin >> 3;
        int off = (lin & 7) * 16;
        const char* g = (const char*)g_eH + (size_t)(n0 + row) * (D * 2) + k0 * 2 + off;
        uint32_t s = sb + (uint32_t)(row * BPITCH) + off;
        asm volatile("cp.async.cg.shared.global [%0], [%1], 16;" :: "r"(s), "l"(g));
    }
}

// ---------------------------------------------------------------------------
// pass-1: fp16 MMA (fp16 accumulate) + best-2(+3rd value) candidate gen
// 256 threads, warps 4(m) x 2(n) over 128x128 output tiles. k64 chunks,
// 2-stage cp.async pipeline; accumulators folded to fp32 every code tile.
// ---------------------------------------------------------------------------
__global__ __launch_bounds__(256, 2)
void argmin_mma(const float* __restrict__ z) {
    extern __shared__ unsigned char sm[];
    const uint32_t sbase = smem_u32(sm);

    const int tid  = threadIdx.x;
    const int lane = tid & 31, wid = tid >> 5;
    const int warp_m = wid & 3, warp_n = wid >> 2;
    const int gid = lane >> 2, tig = lane & 3;
    const int sub = lane >> 3, r7 = lane & 7;
    const int m0 = blockIdx.x * 128;

    // ---- z tile -> fp16 smem (row-major, padded) ----
    for (int i = tid; i < 128 * 64; i += 256) {
        int m = i >> 6, k4 = i & 63;
        float4 v = ((const float4*)(z + (size_t)(m0 + m) * D))[k4];
        uint2 hv;
        hv.x = (uint32_t)__half_as_ushort(__float2half_rn(v.x)) |
               ((uint32_t)__half_as_ushort(__float2half_rn(v.y)) << 16);
        hv.y = (uint32_t)__half_as_ushort(__float2half_rn(v.z)) |
               ((uint32_t)__half_as_ushort(__float2half_rn(v.w)) << 16);
        *(uint2*)(sm + AH_OFF + m * APITCH + k4 * 8) = hv;
    }

    const uint32_t aBase = sbase + AH_OFF +
        (uint32_t)((warp_m * 32 + (sub & 1) * 8 + r7) * APITCH) + (uint32_t)((sub >> 1) * 16);
    const uint32_t bRow =
        (uint32_t)((warp_n * 64 + (sub >> 1) * 8 + r7) * BPITCH) + (uint32_t)((sub & 1) * 16);

    uint32_t acc[2][8][2];   // fp16x2 accumulators
    #pragma unroll
    for (int mt = 0; mt < 2; mt++)
        #pragma unroll
        for (int nt = 0; nt < 8; nt++) { acc[mt][nt][0] = 0u; acc[mt][nt][1] = 0u; }

    float bS1[4], bS2[4], bS3[4];
    int   bI1[4], bI2[4];
    #pragma unroll
    for (int i = 0; i < 4; i++) {
        bS1[i] = CUDART_INF_F; bS2[i] = CUDART_INF_F; bS3[i] = CUDART_INF_F;
        bI1[i] = 0; bI2[i] = 0;
    }

    issue_chunk(sbase, 0, tid);
    asm volatile("cp.async.commit_group;" ::: "memory");

    for (int c = 0; c < 128; c++) {
        asm volatile("cp.async.wait_group 0;" ::: "memory");
        __syncthreads();   // chunk c resident & visible; all warps past compute(c-1)

        if (c + 1 < 128) {
            issue_chunk(sbase, c + 1, tid);
            asm volatile("cp.async.commit_group;" ::: "memory");
        }

        const uint32_t kA = (uint32_t)((c & 3) * 128);
        const uint32_t bStage = sbase + BB_OFF + (uint32_t)(c & 1) * BSTAGE;

        #pragma unroll
        for (int ks = 0; ks < 4; ks++) {
            uint32_t ah[2][4];
            #pragma unroll
            for (int mt = 0; mt < 2; mt++)
                ldsm4(ah[mt], aBase + (uint32_t)(mt * 16 * APITCH) + kA + ks * 32);
            uint32_t bh[8][2];
            #pragma unroll
            for (int p = 0; p < 4; p++) {
                uint32_t t[4];
                ldsm4(t, bStage + bRow + (uint32_t)(p * 16 * BPITCH) + ks * 32);
                bh[2*p][0] = t[0]; bh[2*p][1] = t[1];
                bh[2*p+1][0] = t[2]; bh[2*p+1][1] = t[3];
            }
            #pragma unroll
            for (int mt = 0; mt < 2; mt++)
                #pragma unroll
                for (int nt = 0; nt < 8; nt++)
                    mma16816h(acc[mt][nt], ah[mt], bh[nt][0], bh[nt][1]);
        }

        if ((c & 3) == 3) {   // code tile complete: fold into best-3, reset acc
            const int n0 = (c >> 2) * 128;
            #pragma unroll
            for (int nt = 0; nt < 8; nt++) {
                int nb = n0 + warp_n * 64 + nt * 8 + tig * 2;
                float2 en = *(const float2*)&g_eNormHalf[nb];
                #pragma unroll
                for (int mt = 0; mt < 2; mt++) {
                    #pragma unroll
                    for (int half = 0; half < 2; half++) {
                        int lr = mt * 2 + half;
                        float2 dv = __half22float2(*(__half2*)&acc[mt][nt][half]);
                        float sa  = en.x - dv.x;
                        float sb2 = en.y - dv.y;
                        if (sa < bS1[lr]) { bS3[lr] = bS2[lr]; bS2[lr] = bS1[lr]; bI2[lr] = bI1[lr]; bS1[lr] = sa; bI1[lr] = nb; }
                        else if (sa < bS2[lr]) { bS3[lr] = bS2[lr]; bS2[lr] = sa; bI2[lr] = nb; }
                        else if (sa < bS3[lr]) { bS3[lr] = sa; }
                        if (sb2 < bS1[lr]) { bS3[lr] = bS2[lr]; bS2[lr] = bS1[lr]; bI2[lr] = bI1[lr]; bS1[lr] = sb2; bI1[lr] = nb + 1; }
                        else if (sb2 < bS2[lr]) { bS3[lr] = bS2[lr]; bS2[lr] = sb2; bI2[lr] = nb + 1; }
                        else if (sb2 < bS3[lr]) { bS3[lr] = sb2; }
                    }
                    acc[mt][nt][0] = 0u; acc[mt][nt][1] = 0u;
                }
            }
        }
    }
    __syncthreads();   // compute done; reduction aliases B stages

    float* rS1 = (float*)(sm + RED_OFF);
    int*   rI1 = (int*)  (sm + RED_OFF + 4096);
    float* rS2 = (float*)(sm + RED_OFF + 8192);
    int*   rI2 = (int*)  (sm + RED_OFF + 12288);
    float* rS3 = (float*)(sm + RED_OFF + 16384);
    const int slot = warp_n * 4 + tig;
    #pragma unroll
    for (int lr = 0; lr < 4; lr++) {
        int r = warp_m * 32 + (lr >> 1) * 16 + (lr & 1) * 8 + gid;
        rS1[r * 8 + slot] = bS1[lr];
        rI1[r * 8 + slot] = bI1[lr];
        rS2[r * 8 + slot] = bS2[lr];
        rI2[r * 8 + slot] = bI2[lr];
        rS3[r * 8 + slot] = bS3[lr];
    }
    __syncthreads();
    if (tid < 128) {
        const int m = m0 + tid;
        float gbs = CUDART_INF_F; int gbi = 0x7FFFFFFF;
        #pragma unroll
        for (int s = 0; s < 8; s++) {
            float v = rS1[tid * 8 + s]; int i = rI1[tid * 8 + s];
            if (v < gbs || (v == gbs && i < gbi)) { gbs = v; gbi = i; }
        }
        g_idx[m] = gbi;
        const float win = gbs + WINDOW;
        int cand[16]; int cc = 0; bool fallback = false;
        #pragma unroll
        for (int s = 0; s < 8; s++) {
            if (rS1[tid * 8 + s] <= win) cand[cc++] = rI1[tid * 8 + s];
            if (rS2[tid * 8 + s] <= win) cand[cc++] = rI2[tid * 8 + s];
            if (rS3[tid * 8 + s] <= win) fallback = true;
        }
        if (fallback) {
            int p = atomicAdd(&g_fullCount, 1);
            g_fullList[p] = m;
        } else if (cc > 1) {
            int p = atomicAdd(&g_ambCount, 1);
            g_ambList[p] = m;
            g_candCnt[p] = cc;
            for (int j = 0; j < cc; j++) g_candList[p * 16 + j] = cand[j];
        }
    }
}

// ---------------------------------------------------------------------------
// fixcand: exact fp32 score per candidate + 16-lane min-reduce, writes g_idx.
// ---------------------------------------------------------------------------
__global__ void fixcand_kernel(const float* __restrict__ z, const float* __restrict__ e) {
    const int cnt = g_ambCount;
    const int gsz = (gridDim.x * 256) >> 4;
    const int ci  = threadIdx.x & 15;
    for (int ti = (blockIdx.x * 256 + threadIdx.x) >> 4; ti < cnt; ti += gsz) {
        int m  = g_ambList[ti];
        int cc = g_candCnt[ti];
        float s = CUDART_INF_F;
        int   n = 0x7FFFFFFF;
        if (ci < cc) {
            n = g_candList[ti * 16 + ci];
            s = exact_score(z + (size_t)m * D, e, n);
        }
        uint32_t fb = __float_as_uint(s);
        fb = (fb & 0x80000000u) ? ~fb : (fb | 0x80000000u);
        unsigned long long key = ((unsigned long long)fb << 32) | (uint32_t)n;
        #pragma unroll
        for (int o = 8; o; o >>= 1) {
            unsigned long long other = __shfl_xor_sync(0xFFFFFFFFu, key, o);
            if (other < key) key = other;
        }
        if (ci == 0) g_idx[m] = (int)(key & 0xFFFFFFFFu);
    }
}

// ---------------------------------------------------------------------------
// fallback: exact full-scan for tokens with possible hidden candidates
// ---------------------------------------------------------------------------
__global__ void fixfull_kernel(const float* __restrict__ z, const float* __restrict__ e) {
    __shared__ __align__(16) float sz[D];
    __shared__ float rs[256];
    __shared__ int   ri[256];
    const int tid = threadIdx.x;
    const int cnt = g_fullCount;
    for (int li = blockIdx.x; li < cnt; li += gridDim.x) {
        int m = g_fullList[li];
        sz[tid] = z[(size_t)m * D + tid];
        __syncthreads();
        float bs = CUDART_INF_F;
        int   bi = 0x7FFFFFFF;
        for (int rep = 0; rep < NE / 256; rep++) {
            int n = rep * 256 + tid;
            float s = exact_score(sz, e, n);
            if (s < bs || (s == bs && n < bi)) { bs = s; bi = n; }
        }
        rs[tid] = bs; ri[tid] = bi;
        __syncthreads();
        if (tid == 0) {
            float b = rs[0]; int i = ri[0];
            for (int t = 1; t < 256; t++)
                if (rs[t] < b || (rs[t] == b && ri[t] < i)) { b = rs[t]; i = ri[t]; }
            g_idx[m] = i;
        }
        __syncthreads();
    }
}

// ---------------------------------------------------------------------------
// gather
// ---------------------------------------------------------------------------
__global__ void gather_kernel(const float* __restrict__ e,
                              float* __restrict__ out, int write_idx_tail) {
    int t   = blockIdx.x * blockDim.x + threadIdx.x;
    int row = t >> 6;
    int c   = t & 63;
    int idx = g_idx[row];
    ((float4*)out)[t] = ((const float4*)(e + (size_t)idx * D))[c];
    if (write_idx_tail && c == 0) out[NT * D + row] = (float)idx;
}

extern "C" void kernel_launch(void* const* d_in, const int* in_sizes, int n_in,
                              void* d_out, int out_size) {
    const float* z = (const float*)d_in[0];
    const float* e = (const float*)d_in[1];
    float* out = (float*)d_out;
    int write_idx_tail = (out_size >= NT * D + NT) ? 1 : 0;

    cudaFuncSetAttribute(argmin_mma, cudaFuncAttributeMaxDynamicSharedMemorySize, SMEM_TOTAL);

    prep_kernel<<<NE / 8, 256>>>(e);
    argmin_mma<<<NT / 128, 256, SMEM_TOTAL>>>(z);
    fixcand_kernel<<<148, 256>>>(z, e);
    fixfull_kernel<<<148, 256>>>(z, e);
    gather_kernel<<<(NT * (D / 4)) / 256, 256>>>(e, out, write_idx_tail);
}

// round 14
// speedup vs baseline: 1.3482x; 1.3482x over previous
#include <cuda_runtime.h>
#include <cuda_fp16.h>
#include <cstdint>
#include <math_constants.h>

#define D       256
#define NT      65536
#define NE      4096
#define WINDOW  0.08f

// ---- smem layout (bytes) ----
#define APITCH  528                       // 264 halves per A row (256 data + 8 pad)
#define AH_OFF  0
#define BB_OFF  (128 * APITCH)            // 67584
#define BPITCH  144                       // 72 halves per B row (64 data + 8 pad)
#define BSTAGE  (128 * BPITCH)            // 18432
#define NSTAGE  2
#define RED_OFF BB_OFF                    // reduction arrays alias B stages
#define SMEM_TOTAL (BB_OFF + NSTAGE * BSTAGE)   // 104448 (~102KB) -> 2 CTAs/SM

__device__ float  g_eNormHalf[NE];
__device__ int    g_idx[NT];
__device__ int    g_ambCount;
__device__ int    g_fullCount;
__device__ int    g_ambList[NT];
__device__ int    g_fullList[NT];
__device__ int    g_candList[NT * 16];
__device__ int    g_candCnt[NT];
__device__ __half g_eH[NE * D];

// ---------------- helpers ----------------
__device__ __forceinline__ uint32_t smem_u32(const void* p) {
    uint32_t a;
    asm("{ .reg .u64 t; cvta.to.shared.u64 t, %1; cvt.u32.u64 %0, t; }" : "=r"(a) : "l"(p));
    return a;
}
__device__ __forceinline__ void ldsm4(uint32_t (&r)[4], uint32_t a) {
    asm volatile("ldmatrix.sync.aligned.m8n8.x4.shared.b16 {%0,%1,%2,%3}, [%4];"
                 : "=r"(r[0]), "=r"(r[1]), "=r"(r[2]), "=r"(r[3]) : "r"(a));
}
__device__ __forceinline__ void mma16816(float (&c)[4], const uint32_t (&a)[4],
                                         uint32_t b0, uint32_t b1) {
    asm volatile("mma.sync.aligned.m16n8k16.row.col.f32.f16.f16.f32 "
                 "{%0,%1,%2,%3}, {%4,%5,%6,%7}, {%8,%9}, {%0,%1,%2,%3};"
                 : "+f"(c[0]), "+f"(c[1]), "+f"(c[2]), "+f"(c[3])
                 : "r"(a[0]), "r"(a[1]), "r"(a[2]), "r"(a[3]), "r"(b0), "r"(b1));
}

// exact fp32 score in the VALIDATED order (matches reference argmin behavior)
__device__ __forceinline__ float exact_score(const float* __restrict__ zrow,
                                             const float* __restrict__ e, int n) {
    float acc = 0.f;
    const float4* er = (const float4*)(e + (size_t)n * D);
    const float4* zr = (const float4*)zrow;
    #pragma unroll 8
    for (int k4 = 0; k4 < D / 4; k4++) {
        float4 ee = er[k4], zz = zr[k4];
        acc = __fmaf_rn(zz.x, ee.x, acc);
        acc = __fmaf_rn(zz.y, ee.y, acc);
        acc = __fmaf_rn(zz.z, ee.z, acc);
        acc = __fmaf_rn(zz.w, ee.w, acc);
    }
    return g_eNormHalf[n] - acc;
}

// ---------------------------------------------------------------------------
// prep: 0.5*||e||^2 AND fp16 image of e in one pass; zero counters.
// ---------------------------------------------------------------------------
__global__ void prep_kernel(const float* __restrict__ e) {
    int row  = blockIdx.x * (blockDim.x >> 5) + (threadIdx.x >> 5);
    int lane = threadIdx.x & 31;
    if (blockIdx.x == 0 && threadIdx.x == 0) { g_ambCount = 0; g_fullCount = 0; }
    const float4* p = (const float4*)(e + (size_t)row * D);
    float s = 0.f;
    #pragma unroll
    for (int i = 0; i < 2; i++) {
        int c4 = lane + i * 32;
        float4 v = p[c4];
        s += v.x * v.x + v.y * v.y + v.z * v.z + v.w * v.w;
        uint2 hv;
        hv.x = (uint32_t)__half_as_ushort(__float2half_rn(v.x)) |
               ((uint32_t)__half_as_ushort(__float2half_rn(v.y)) << 16);
        hv.y = (uint32_t)__half_as_ushort(__float2half_rn(v.z)) |
               ((uint32_t)__half_as_ushort(__float2half_rn(v.w)) << 16);
        *(uint2*)(g_eH + (size_t)row * D + c4 * 4) = hv;
    }
    #pragma unroll
    for (int o = 16; o; o >>= 1) s += __shfl_xor_sync(0xFFFFFFFFu, s, o);
    if (lane == 0) g_eNormHalf[row] = 0.5f * s;
}

// ---------------------------------------------------------------------------
// cp.async fill of one e k-chunk (128 codes x 64 dims fp16) into stage c%2
// ---------------------------------------------------------------------------
__device__ __forceinline__ void issue_chunk(uint32_t sbase, int c, int tid) {
    const int n0 = (c >> 2) * 128;
    const int k0 = (c & 3) * 64;
    const uint32_t sb = sbase + BB_OFF + (uint32_t)(c & 1) * BSTAGE;
    #pragma unroll
    for (int j = 0; j < 4; j++) {
        int lin = tid + j * 256;            // 0..1023
        int row = lin >> 3;
        int off = (lin & 7) * 16;
        const char* g = (const char*)g_eH + (size_t)(n0 + row) * (D * 2) + k0 * 2 + off;
        uint32_t s = sb + (uint32_t)(row * BPITCH) + off;
        asm volatile("cp.async.cg.shared.global [%0], [%1], 16;" :: "r"(s), "l"(g));
    }
}

// ---------------------------------------------------------------------------
// pass-1: fp16 MMA (fp32 accumulate) + best-2(+3rd value) candidate gen
// + fused quantized-output write for the pass-1 winners.
// 256 threads, warps 4(m) x 2(n) over 128x128 output tiles.
// ---------------------------------------------------------------------------
__global__ __launch_bounds__(256, 2)
void argmin_mma(const float* __restrict__ z, const float* __restrict__ e,
                float* __restrict__ out, int write_idx_tail) {
    extern __shared__ unsigned char sm[];
    const uint32_t sbase = smem_u32(sm);

    const int tid  = threadIdx.x;
    const int lane = tid & 31, wid = tid >> 5;
    const int warp_m = wid & 3, warp_n = wid >> 2;
    const int gid = lane >> 2, tig = lane & 3;
    const int sub = lane >> 3, r7 = lane & 7;
    const int m0 = blockIdx.x * 128;

    // ---- z tile -> fp16 smem (row-major, padded) ----
    for (int i = tid; i < 128 * 64; i += 256) {
        int m = i >> 6, k4 = i & 63;
        float4 v = ((const float4*)(z + (size_t)(m0 + m) * D))[k4];
        uint2 hv;
        hv.x = (uint32_t)__half_as_ushort(__float2half_rn(v.x)) |
               ((uint32_t)__half_as_ushort(__float2half_rn(v.y)) << 16);
        hv.y = (uint32_t)__half_as_ushort(__float2half_rn(v.z)) |
               ((uint32_t)__half_as_ushort(__float2half_rn(v.w)) << 16);
        *(uint2*)(sm + AH_OFF + m * APITCH + k4 * 8) = hv;
    }

    const uint32_t aBase = sbase + AH_OFF +
        (uint32_t)((warp_m * 32 + (sub & 1) * 8 + r7) * APITCH) + (uint32_t)((sub >> 1) * 16);
    const uint32_t bRow =
        (uint32_t)((warp_n * 64 + (sub >> 1) * 8 + r7) * BPITCH) + (uint32_t)((sub & 1) * 16);

    float acc[2][8][4];
    #pragma unroll
    for (int mt = 0; mt < 2; mt++)
        #pragma unroll
        for (int nt = 0; nt < 8; nt++)
            #pragma unroll
            for (int q = 0; q < 4; q++) acc[mt][nt][q] = 0.f;

    float bS1[4], bS2[4], bS3[4];
    int   bI1[4], bI2[4];
    #pragma unroll
    for (int i = 0; i < 4; i++) {
        bS1[i] = CUDART_INF_F; bS2[i] = CUDART_INF_F; bS3[i] = CUDART_INF_F;
        bI1[i] = 0; bI2[i] = 0;
    }

    issue_chunk(sbase, 0, tid);
    asm volatile("cp.async.commit_group;" ::: "memory");

    for (int c = 0; c < 128; c++) {
        asm volatile("cp.async.wait_group 0;" ::: "memory");
        __syncthreads();   // chunk c resident & visible; all warps past compute(c-1)

        if (c + 1 < 128) {
            issue_chunk(sbase, c + 1, tid);
            asm volatile("cp.async.commit_group;" ::: "memory");
        }

        const uint32_t kA = (uint32_t)((c & 3) * 128);
        const uint32_t bStage = sbase + BB_OFF + (uint32_t)(c & 1) * BSTAGE;

        #pragma unroll
        for (int ks = 0; ks < 4; ks++) {
            uint32_t ah[2][4];
            #pragma unroll
            for (int mt = 0; mt < 2; mt++)
                ldsm4(ah[mt], aBase + (uint32_t)(mt * 16 * APITCH) + kA + ks * 32);
            uint32_t bh[8][2];
            #pragma unroll
            for (int p = 0; p < 4; p++) {
                uint32_t t[4];
                ldsm4(t, bStage + bRow + (uint32_t)(p * 16 * BPITCH) + ks * 32);
                bh[2*p][0] = t[0]; bh[2*p][1] = t[1];
                bh[2*p+1][0] = t[2]; bh[2*p+1][1] = t[3];
            }
            #pragma unroll
            for (int mt = 0; mt < 2; mt++)
                #pragma unroll
                for (int nt = 0; nt < 8; nt++)
                    mma16816(acc[mt][nt], ah[mt], bh[nt][0], bh[nt][1]);
        }

        if ((c & 3) == 3) {   // code tile complete: fold into best-3, reset acc
            const int n0 = (c >> 2) * 128;
            #pragma unroll
            for (int nt = 0; nt < 8; nt++) {
                int nb = n0 + warp_n * 64 + nt * 8 + tig * 2;
                float2 en = *(const float2*)&g_eNormHalf[nb];
                #pragma unroll
                for (int mt = 0; mt < 2; mt++) {
                    #pragma unroll
                    for (int half = 0; half < 2; half++) {
                        int lr = mt * 2 + half;
                        float sa  = (half ? en.x - acc[mt][nt][2] : en.x - acc[mt][nt][0]);
                        float sb2 = (half ? en.y - acc[mt][nt][3] : en.y - acc[mt][nt][1]);
                        if (sa < bS1[lr]) { bS3[lr] = bS2[lr]; bS2[lr] = bS1[lr]; bI2[lr] = bI1[lr]; bS1[lr] = sa; bI1[lr] = nb; }
                        else if (sa < bS2[lr]) { bS3[lr] = bS2[lr]; bS2[lr] = sa; bI2[lr] = nb; }
                        else if (sa < bS3[lr]) { bS3[lr] = sa; }
                        if (sb2 < bS1[lr]) { bS3[lr] = bS2[lr]; bS2[lr] = bS1[lr]; bI2[lr] = bI1[lr]; bS1[lr] = sb2; bI1[lr] = nb + 1; }
                        else if (sb2 < bS2[lr]) { bS3[lr] = bS2[lr]; bS2[lr] = sb2; bI2[lr] = nb + 1; }
                        else if (sb2 < bS3[lr]) { bS3[lr] = sb2; }
                    }
                    acc[mt][nt][0] = 0.f; acc[mt][nt][1] = 0.f;
                    acc[mt][nt][2] = 0.f; acc[mt][nt][3] = 0.f;
                }
            }
        }
    }
    __syncthreads();   // compute done; reduction aliases B stages

    float* rS1 = (float*)(sm + RED_OFF);
    int*   rI1 = (int*)  (sm + RED_OFF + 4096);
    float* rS2 = (float*)(sm + RED_OFF + 8192);
    int*   rI2 = (int*)  (sm + RED_OFF + 12288);
    float* rS3 = (float*)(sm + RED_OFF + 16384);
    int*   sIdx = (int*) (sm + RED_OFF + 20480);
    const int slot = warp_n * 4 + tig;
    #pragma unroll
    for (int lr = 0; lr < 4; lr++) {
        int r = warp_m * 32 + (lr >> 1) * 16 + (lr & 1) * 8 + gid;
        rS1[r * 8 + slot] = bS1[lr];
        rI1[r * 8 + slot] = bI1[lr];
        rS2[r * 8 + slot] = bS2[lr];
        rI2[r * 8 + slot] = bI2[lr];
        rS3[r * 8 + slot] = bS3[lr];
    }
    __syncthreads();
    if (tid < 128) {
        const int m = m0 + tid;
        float gbs = CUDART_INF_F; int gbi = 0x7FFFFFFF;
        #pragma unroll
        for (int s = 0; s < 8; s++) {
            float v = rS1[tid * 8 + s]; int i = rI1[tid * 8 + s];
            if (v < gbs || (v == gbs && i < gbi)) { gbs = v; gbi = i; }
        }
        g_idx[m] = gbi;
        sIdx[tid] = gbi;
        if (write_idx_tail) out[(size_t)NT * D + m] = (float)gbi;
        const float win = gbs + WINDOW;
        int cand[16]; int cc = 0; bool fallback = false;
        #pragma unroll
        for (int s = 0; s < 8; s++) {
            if (rS1[tid * 8 + s] <= win) cand[cc++] = rI1[tid * 8 + s];
            if (rS2[tid * 8 + s] <= win) cand[cc++] = rI2[tid * 8 + s];
            if (rS3[tid * 8 + s] <= win) fallback = true;
        }
        if (fallback) {
            int p = atomicAdd(&g_fullCount, 1);
            g_fullList[p] = m;
        } else if (cc > 1) {
            int p = atomicAdd(&g_ambCount, 1);
            g_ambList[p] = m;
            g_candCnt[p] = cc;
            for (int j = 0; j < cc; j++) g_candList[p * 16 + j] = cand[j];
        }
    }
    __syncthreads();

    // ---- fused gather: write quantized rows for pass-1 winners ----
    const float4* e4 = (const float4*)e;
    float4* out4 = (float4*)out;
    for (int t = tid; t < 128 * 64; t += 256) {
        int row = t >> 6, cc4 = t & 63;
        int idx = sIdx[row];
        out4[(size_t)(m0 + row) * 64 + cc4] = e4[(size_t)idx * 64 + cc4];
    }
}

// ---------------------------------------------------------------------------
// fixcand: exact fp32 score per candidate + 16-lane min-reduce, writes g_idx.
// ---------------------------------------------------------------------------
__global__ void fixcand_kernel(const float* __restrict__ z, const float* __restrict__ e) {
    const int cnt = g_ambCount;
    const int gsz = (gridDim.x * 256) >> 4;
    const int ci  = threadIdx.x & 15;
    for (int ti = (blockIdx.x * 256 + threadIdx.x) >> 4; ti < cnt; ti += gsz) {
        int m  = g_ambList[ti];
        int cc = g_candCnt[ti];
        float s = CUDART_INF_F;
        int   n = 0x7FFFFFFF;
        if (ci < cc) {
            n = g_candList[ti * 16 + ci];
            s = exact_score(z + (size_t)m * D, e, n);
        }
        uint32_t fb = __float_as_uint(s);
        fb = (fb & 0x80000000u) ? ~fb : (fb | 0x80000000u);
        unsigned long long key = ((unsigned long long)fb << 32) | (uint32_t)n;
        #pragma unroll
        for (int o = 8; o; o >>= 1) {
            unsigned long long other = __shfl_xor_sync(0xFFFFFFFFu, key, o);
            if (other < key) key = other;
        }
        if (ci == 0) g_idx[m] = (int)(key & 0xFFFFFFFFu);
    }
}

// ---------------------------------------------------------------------------
// fallback: exact full-scan for tokens with possible hidden candidates
// ---------------------------------------------------------------------------
__global__ void fixfull_kernel(const float* __restrict__ z, const float* __restrict__ e) {
    __shared__ __align__(16) float sz[D];
    __shared__ float rs[256];
    __shared__ int   ri[256];
    const int tid = threadIdx.x;
    const int cnt = g_fullCount;
    for (int li = blockIdx.x; li < cnt; li += gridDim.x) {
        int m = g_fullList[li];
        sz[tid] = z[(size_t)m * D + tid];
        __syncthreads();
        float bs = CUDART_INF_F;
        int   bi = 0x7FFFFFFF;
        for (int rep = 0; rep < NE / 256; rep++) {
            int n = rep * 256 + tid;
            float s = exact_score(sz, e, n);
            if (s < bs || (s == bs && n < bi)) { bs = s; bi = n; }
        }
        rs[tid] = bs; ri[tid] = bi;
        __syncthreads();
        if (tid == 0) {
            float b = rs[0]; int i = ri[0];
            for (int t = 1; t < 256; t++)
                if (rs[t] < b || (rs[t] == b && ri[t] < i)) { b = rs[t]; i = ri[t]; }
            g_idx[m] = i;
        }
        __syncthreads();
    }
}

// ---------------------------------------------------------------------------
// fixout: rewrite output rows (and index tail) for corrected tokens
// ---------------------------------------------------------------------------
__global__ void fixout_kernel(const float* __restrict__ e,
                              float* __restrict__ out, int write_idx_tail) {
    const int ac = g_ambCount, fc = g_fullCount;
    const int total = (ac + fc) * 64;
    for (int w = blockIdx.x * 256 + threadIdx.x; w < total; w += gridDim.x * 256) {
        int li = w >> 6, c = w & 63;
        int m = (li < ac) ? g_ambList[li] : g_fullList[li - ac];
        int idx = g_idx[m];
        ((float4*)out)[(size_t)m * 64 + c] = ((const float4*)e)[(size_t)idx * 64 + c];
        if (c == 0 && write_idx_tail) out[(size_t)NT * D + m] = (float)idx;
    }
}

extern "C" void kernel_launch(void* const* d_in, const int* in_sizes, int n_in,
                              void* d_out, int out_size) {
    const float* z = (const float*)d_in[0];
    const float* e = (const float*)d_in[1];
    float* out = (float*)d_out;
    int write_idx_tail = (out_size >= NT * D + NT) ? 1 : 0;

    cudaFuncSetAttribute(argmin_mma, cudaFuncAttributeMaxDynamicSharedMemorySize, SMEM_TOTAL);

    prep_kernel<<<NE / 8, 256>>>(e);
    argmin_mma<<<NT / 128, 256, SMEM_TOTAL>>>(z, e, out, write_idx_tail);
    fixcand_kernel<<<64, 256>>>(z, e);
    fixfull_kernel<<<64, 256>>>(z, e);
    fixout_kernel<<<64, 256>>>(e, out, write_idx_tail);
}